// round 12
// baseline (speedup 1.0000x reference)
#include <cuda_runtime.h>
#include <cuda_fp16.h>
#include <cstdint>

#define SS 2048
#define BB 64
#define DD 512

// ---------------- device scratch (static; no runtime allocs) ----------------
__device__ float g_u[BB * DD];                      // u[b,a] = input.W1x + b1
__device__ __align__(16) __half g_whi[DD * DD];     // W1_src (fp16 rne), K-major [a][d]
__device__ float g_part[8 * BB * DD];               // ctx partials (8 s-slices)

// ---------------- helpers ----------------
__device__ __forceinline__ uint32_t smem_u32(const void* p) {
    uint32_t a;
    asm("{ .reg .u64 t; cvta.to.shared.u64 t, %1; cvt.u32.u64 %0, t; }" : "=r"(a) : "l"(p));
    return a;
}
__device__ __forceinline__ uint32_t packh2(__half a, __half b) {
    __half2 h = __halves2half2(a, b);
    return *reinterpret_cast<uint32_t*>(&h);
}
__device__ __forceinline__ void cp16(uint32_t dst, const void* src) {
    asm volatile("cp.async.cg.shared.global [%0], [%1], 16;" :: "r"(dst), "l"(src) : "memory");
}
__device__ __forceinline__ float tanh_f(float x) {
    float e = __expf(2.f * x);
    return 1.f - __fdividef(2.f, e + 1.f);
}

#define LDSM4(r, addr) \
    asm volatile("ldmatrix.sync.aligned.m8n8.x4.shared.b16 {%0,%1,%2,%3}, [%4];" \
        : "=r"((r)[0]), "=r"((r)[1]), "=r"((r)[2]), "=r"((r)[3]) : "r"(addr))

#define MMA(d, a, b) \
    asm volatile("mma.sync.aligned.m16n8k16.row.col.f32.f16.f16.f32 " \
        "{%0,%1,%2,%3}, {%4,%5,%6,%7}, {%8,%9}, {%0,%1,%2,%3};" \
        : "+f"((d)[0]), "+f"((d)[1]), "+f"((d)[2]), "+f"((d)[3]) \
        : "r"((a)[0]), "r"((a)[1]), "r"((a)[2]), "r"((a)[3]), "r"((b)[0]), "r"((b)[1]))

#define BARG(id) asm volatile("bar.sync %0, 128;" :: "r"(id) : "memory")

// ---------------- smem layout for gemm_k ----------------
#define U_OFF    0
#define W2_OFF   2048
#define RED_OFF  4096            // 4 planes x 128 f = 2048 B
#define A_O      6144
#define A_ROWB   1040            // 512 fp16 = 1024B + 16B pad -> conflict-free LDSM
#define A_SZ     (128 * A_ROWB)  // 133120
#define B_O      (A_O + A_SZ)    // 139264
#define ROWB2    144             // B row: 128B data (k64 fp16) + 16B pad
#define GST      (64 * ROWB2)    // 9216 per group per stage (64 n-rows now)
#define STG_ALL  (4 * GST)       // 36864 per stage (4 groups)
#define NSTAGE   2
#define DYN_SMEM (B_O + NSTAGE * STG_ALL)   // 212992

// ==================== prep: u[b,a] ====================
__global__ void prep_u_k(const float* __restrict__ input, const float* __restrict__ W1,
                         const float* __restrict__ b1) {
    __shared__ float inp[DD];
    int blk = blockIdx.x, tid = threadIdx.x;
    inp[tid] = input[blk * DD + tid];
    inp[tid + 256] = input[blk * DD + tid + 256];
    __syncthreads();
    for (int a = tid; a < DD; a += 256) {
        const float* w = W1 + (size_t)a * (2 * DD);
        float acc = b1[a];
        #pragma unroll 8
        for (int d = 0; d < DD; d++) acc += inp[d] * w[d];
        g_u[blk * DD + a] = acc;
    }
}

// ==================== prep: W fp16 round ====================
__global__ void prep_w_k(const float* __restrict__ W1) {
    int base = blockIdx.x * 16384, tid = threadIdx.x;
    for (int i = tid; i < 16384; i += 256) {
        int idx = base + i;
        int a = idx >> 9, j = idx & 511;
        g_whi[idx] = __float2half_rn(W1[(size_t)a * (2 * DD) + DD + j]);
    }
}

__global__ void dummy_k() {}

// ==== GEMM (fp16, 16 warps, warp tile m32 x n64, group B pipelines) + fused epilogue ====
__global__ void __launch_bounds__(512, 1)
gemm_k(const float* __restrict__ src, float* __restrict__ scores, const float* __restrict__ W2) {
    extern __shared__ char sm[];
    uint32_t smb = smem_u32(sm);
    int tid = threadIdx.x, lid = tid & 31, wid = tid >> 5;
    int wm = wid & 3, wn = wid >> 2;      // 4 m-warps x 4 n-warp-groups (n64 each)
    int gtid = tid & 127;                 // thread-in-group
    int b = blockIdx.y;
    int s0 = blockIdx.x * 128;

    float* u_sm  = (float*)(sm + U_OFF);
    float* w2_sm = (float*)(sm + W2_OFF);
    u_sm[tid] = g_u[b * DD + tid];
    w2_sm[tid] = W2[tid];

    const float* srcb = src + (size_t)b * DD;   // src[s][b][d]; s-stride = BB*DD

    // ---- load + convert entire A tile (128 x 512 fp32 -> fp16) into smem, once ----
    {
        const int c4 = tid & 127;
        const int rb = tid >> 7;              // 0..3
        #pragma unroll 1
        for (int t8 = 0; t8 < 4; t8++) {
            float4 v[8];
            #pragma unroll
            for (int j = 0; j < 8; j++) {
                int r = rb + 4 * (t8 * 8 + j);
                v[j] = *(const float4*)(srcb + (size_t)(s0 + r) * (BB * DD) + c4 * 4);
            }
            #pragma unroll
            for (int j = 0; j < 8; j++) {
                int r = rb + 4 * (t8 * 8 + j);
                *(uint2*)(sm + A_O + r * A_ROWB + c4 * 8) = make_uint2(
                    packh2(__float2half_rn(v[j].x), __float2half_rn(v[j].y)),
                    packh2(__float2half_rn(v[j].z), __float2half_rn(v[j].w)));
            }
        }
    }

    // ---- group-private B pipeline: this group's 64 n-rows (4 cp16 / thread / chunk) ----
    // slot q = gtid + 128*t : row = q>>3 (0..63), sg = q&7
    const uint32_t bdst0 = smb + B_O + (uint32_t)(wn * GST);
    const __half* bsrc0 = g_whi + (size_t)(wn * 64) * DD;

    // prologue: stage 0 = chunk 0 (nt=0, ck=0)
    {
        #pragma unroll
        for (int t = 0; t < 4; t++) {
            int q = gtid + 128 * t, row = q >> 3, sg = q & 7;
            cp16(bdst0 + (uint32_t)(row * ROWB2 + sg * 16),
                 bsrc0 + (size_t)row * DD + sg * 8);
        }
        asm volatile("cp.async.commit_group;" ::: "memory");
    }
    __syncthreads();   // A tile + u/w2 visible to everyone

    // hoisted LDSM lane addressing
    const uint32_t a_base = smb + A_O + (uint32_t)((wm * 32 + (lid & 15)) * A_ROWB + (lid >> 4) * 16);
    const uint32_t b_lane = (uint32_t)(((((lid >> 4) << 3) | (lid & 7)) * ROWB2) + ((lid >> 3) & 1) * 16);
    const uint32_t b_grp  = bdst0 + b_lane;

    float sc[4] = {0.f, 0.f, 0.f, 0.f};
    float acc[2][8][4];
    #pragma unroll
    for (int i = 0; i < 2; i++)
        #pragma unroll
        for (int j = 0; j < 8; j++)
            #pragma unroll
            for (int k = 0; k < 4; k++) acc[i][j][k] = 0.f;

    for (int idx = 0; idx < 16; idx++) {
        int nt = idx >> 3, ck = idx & 7;
        int st = idx & 1;

        asm volatile("cp.async.wait_group 0;" ::: "memory");
        BARG(wn + 1);   // group-scoped: B stage ready + all group warps done with other stage

        // prefetch chunk idx+1 into the other stage (always-commit keeps accounting exact)
        {
            int f = idx + 1;
            if (f < 16) {
                int fnt = f >> 3, fck = f & 7;
                const __half* wsrc = bsrc0 + (size_t)(fnt * 256) * DD + fck * 64;
                uint32_t dst = bdst0 + (uint32_t)((st ^ 1) * STG_ALL);
                #pragma unroll
                for (int t = 0; t < 4; t++) {
                    int q = gtid + 128 * t, row = q >> 3, sg = q & 7;
                    cp16(dst + (uint32_t)(row * ROWB2 + sg * 16),
                         wsrc + (size_t)row * DD + sg * 8);
                }
            }
            asm volatile("cp.async.commit_group;" ::: "memory");
        }

        // ---- MMA: A persistent, B from group stage (k = 64 per idx, n = 64 per warp) ----
        {
            uint32_t a_ck = a_base + (uint32_t)(ck * 128);
            uint32_t b_st = b_grp + (uint32_t)(st * STG_ALL);
            #pragma unroll
            for (int ks = 0; ks < 4; ks++) {
                uint32_t af[2][4];
                uint32_t aoff = a_ck + (uint32_t)(ks * 32);
                LDSM4(af[0], aoff);
                LDSM4(af[1], aoff + 16 * A_ROWB);
                #pragma unroll
                for (int p = 0; p < 4; p++) {
                    uint32_t bh[4];
                    LDSM4(bh, b_st + (uint32_t)(p * (16 * ROWB2) + ks * 32));
                    #pragma unroll
                    for (int mt = 0; mt < 2; mt++) {
                        MMA(acc[mt][2 * p],     af[mt], bh);
                        MMA(acc[mt][2 * p + 1], af[mt], bh + 2);
                    }
                }
            }
        }

        // ---- nt boundary: fold acc into score partials, reset ----
        if (ck == 7) {
            int tq = lid & 3;
            float part[4] = {0.f, 0.f, 0.f, 0.f};
            #pragma unroll
            for (int j = 0; j < 8; j++) {
                int a = nt * 256 + wn * 64 + j * 8 + tq * 2;
                float u0 = u_sm[a], u1 = u_sm[a + 1];
                float w0 = w2_sm[a], w1 = w2_sm[a + 1];
                #pragma unroll
                for (int mt = 0; mt < 2; mt++) {
                    part[mt * 2 + 0] += w0 * tanh_f(acc[mt][j][0] + u0)
                                      + w1 * tanh_f(acc[mt][j][1] + u1);
                    part[mt * 2 + 1] += w0 * tanh_f(acc[mt][j][2] + u0)
                                      + w1 * tanh_f(acc[mt][j][3] + u1);
                }
            }
            #pragma unroll
            for (int i = 0; i < 4; i++) {
                part[i] += __shfl_xor_sync(0xffffffffu, part[i], 1);
                part[i] += __shfl_xor_sync(0xffffffffu, part[i], 2);
                sc[i] += part[i];
            }
            #pragma unroll
            for (int i = 0; i < 2; i++)
                #pragma unroll
                for (int j = 0; j < 8; j++)
                    #pragma unroll
                    for (int k = 0; k < 4; k++) acc[i][j][k] = 0.f;
        }
    }

    // ---- cross-warp (4 n-warp planes) reduction + store scores ----
    float* red = (float*)(sm + RED_OFF);
    __syncthreads();
    if ((lid & 3) == 0) {
        int g = lid >> 2;
        #pragma unroll
        for (int mt = 0; mt < 2; mt++) {
            red[wn * 128 + wm * 32 + mt * 16 + g]     = sc[mt * 2 + 0];
            red[wn * 128 + wm * 32 + mt * 16 + 8 + g] = sc[mt * 2 + 1];
        }
    }
    __syncthreads();
    if (tid < 128)
        scores[(size_t)(s0 + tid) * BB + b] =
            (red[tid] + red[128 + tid]) + (red[256 + tid] + red[384 + tid]);
}

// ==================== softmax over S (in place) ====================
__global__ void softmax_k(float* __restrict__ attn, const unsigned char* __restrict__ mask) {
    __shared__ float red[256];
    int b = blockIdx.x, tid = threadIdx.x;
    float v[8];
    float mx = -1e30f;
    #pragma unroll
    for (int i = 0; i < 8; i++) {
        int s = tid + i * 256;
        float x = attn[(size_t)s * BB + b];
        if (mask[(size_t)s * BB + b]) x = -1e30f;
        v[i] = x;
        mx = fmaxf(mx, x);
    }
    red[tid] = mx; __syncthreads();
    for (int o = 128; o > 0; o >>= 1) { if (tid < o) red[tid] = fmaxf(red[tid], red[tid + o]); __syncthreads(); }
    mx = red[0]; __syncthreads();
    float sum = 0.f;
    #pragma unroll
    for (int i = 0; i < 8; i++) { v[i] = __expf(v[i] - mx); sum += v[i]; }
    red[tid] = sum; __syncthreads();
    for (int o = 128; o > 0; o >>= 1) { if (tid < o) red[tid] += red[tid + o]; __syncthreads(); }
    float inv = __fdividef(1.f, red[0]);
    #pragma unroll
    for (int i = 0; i < 8; i++) attn[(size_t)(tid + i * 256) * BB + b] = v[i] * inv;
}

// ==================== ctx = sum_s attn[s,b] * src[s,b,:]  (float4, deep MLP) ====================
__global__ void ctx_k(const float* __restrict__ src, const float* __restrict__ attn) {
    int b = blockIdx.x, sch = blockIdx.y, tid = threadIdx.x;   // 128 thr, grid (BB, 8)
    const float4* sp = (const float4*)(src + (size_t)b * DD) + tid;
    int s0 = sch * 256;
    float4 a[8];
    #pragma unroll
    for (int j = 0; j < 8; j++) a[j] = make_float4(0.f, 0.f, 0.f, 0.f);
    #pragma unroll 2
    for (int s = s0; s < s0 + 256; s += 8) {
        #pragma unroll
        for (int j = 0; j < 8; j++) {
            float w = attn[(size_t)(s + j) * BB + b];
            float4 v = sp[(size_t)(s + j) * (BB * DD / 4)];
            a[j].x += w * v.x; a[j].y += w * v.y; a[j].z += w * v.z; a[j].w += w * v.w;
        }
    }
    float4 t;
    t.x = ((a[0].x + a[1].x) + (a[2].x + a[3].x)) + ((a[4].x + a[5].x) + (a[6].x + a[7].x));
    t.y = ((a[0].y + a[1].y) + (a[2].y + a[3].y)) + ((a[4].y + a[5].y) + (a[6].y + a[7].y));
    t.z = ((a[0].z + a[1].z) + (a[2].z + a[3].z)) + ((a[4].z + a[5].z) + (a[6].z + a[7].z));
    t.w = ((a[0].w + a[1].w) + (a[2].w + a[3].w)) + ((a[4].w + a[5].w) + (a[6].w + a[7].w));
    ((float4*)g_part)[((sch * BB + b) << 7) + tid] = t;
}

__global__ void red_k(float* __restrict__ out) {
    int i = blockIdx.x * 512 + threadIdx.x;
    float s = 0.f;
    #pragma unroll
    for (int j = 0; j < 8; j++) s += g_part[j * (BB * DD) + i];
    out[i] = s;
}

// ==================== launch ====================
extern "C" void kernel_launch(void* const* d_in, const int* in_sizes, int n_in,
                              void* d_out, int out_size) {
    (void)in_sizes; (void)n_in; (void)out_size;
    const float* input = (const float*)d_in[0];
    const float* src = (const float*)d_in[1];
    const unsigned char* mask = (const unsigned char*)d_in[2];
    const float* W1 = (const float*)d_in[3];
    const float* b1 = (const float*)d_in[4];
    const float* W2 = (const float*)d_in[5];
    float* out = (float*)d_out;          // [ctx: 64*512][attn: 2048*64]
    float* attn = out + BB * DD;

    cudaFuncSetAttribute(gemm_k, cudaFuncAttributeMaxDynamicSharedMemorySize, DYN_SMEM);

    prep_u_k<<<BB, 256>>>(input, W1, b1);        // launch 1
    prep_w_k<<<16, 256>>>(W1);                   // launch 2
    dummy_k<<<1, 32>>>();                        // launch 3
    gemm_k<<<dim3(16, BB), 512, DYN_SMEM>>>(src, attn, W2);   // launch 4
    softmax_k<<<BB, 256>>>(attn, mask);
    ctx_k<<<dim3(BB, 8), 128>>>(src, attn);
    red_k<<<BB, 512>>>(out);
}

// round 14
// speedup vs baseline: 1.2961x; 1.2961x over previous
#include <cuda_runtime.h>
#include <cuda_fp16.h>
#include <cstdint>

#define SS 2048
#define BB 64
#define DD 512

// ---------------- device scratch (static; no runtime allocs) ----------------
__device__ float g_u[BB * DD];                      // u[b,a] = input.W1x + b1
__device__ __align__(16) __half g_whi[DD * DD];     // W1_src (fp16 rne), K-major [a][d]
__device__ float g_part[8 * BB * DD];               // ctx partials (8 s-slices)

// ---------------- helpers ----------------
__device__ __forceinline__ uint32_t smem_u32(const void* p) {
    uint32_t a;
    asm("{ .reg .u64 t; cvta.to.shared.u64 t, %1; cvt.u32.u64 %0, t; }" : "=r"(a) : "l"(p));
    return a;
}
__device__ __forceinline__ uint32_t packh2(__half a, __half b) {
    __half2 h = __halves2half2(a, b);
    return *reinterpret_cast<uint32_t*>(&h);
}
__device__ __forceinline__ void cp16(uint32_t dst, const void* src) {
    asm volatile("cp.async.cg.shared.global [%0], [%1], 16;" :: "r"(dst), "l"(src) : "memory");
}
__device__ __forceinline__ float tanh_f(float x) {
    float e = __expf(2.f * x);
    return 1.f - __fdividef(2.f, e + 1.f);
}

#define LDSM4(r, addr) \
    asm volatile("ldmatrix.sync.aligned.m8n8.x4.shared.b16 {%0,%1,%2,%3}, [%4];" \
        : "=r"((r)[0]), "=r"((r)[1]), "=r"((r)[2]), "=r"((r)[3]) : "r"(addr))

#define MMA(d, a, b) \
    asm volatile("mma.sync.aligned.m16n8k16.row.col.f32.f16.f16.f32 " \
        "{%0,%1,%2,%3}, {%4,%5,%6,%7}, {%8,%9}, {%0,%1,%2,%3};" \
        : "+f"((d)[0]), "+f"((d)[1]), "+f"((d)[2]), "+f"((d)[3]) \
        : "r"((a)[0]), "r"((a)[1]), "r"((a)[2]), "r"((a)[3]), "r"((b)[0]), "r"((b)[1]))

#define BARG(id) asm volatile("bar.sync %0, 128;" :: "r"(id) : "memory")

// ---------------- smem layout for gemm_k (R11 config) ----------------
#define U_OFF    0
#define W2_OFF   2048
#define RED_OFF  4096            // 4 planes x 128 f = 2048 B
#define A_O      6144
#define A_ROWB   1040            // 512 fp16 = 1024B + 16B pad -> conflict-free LDSM
#define A_SZ     (128 * A_ROWB)  // 133120
#define B_O      (A_O + A_SZ)    // 139264
#define ROWB2    144             // B row: 128B data (k64 fp16) + 16B pad
#define GST      (32 * ROWB2)    // 4608 per group per stage
#define STG_ALL  (4 * GST)       // 18432 per stage (4 groups)
#define NSTAGE   3
#define DYN_SMEM (B_O + NSTAGE * STG_ALL)   // 194560

// ==================== prep: u[b,a]  (warp-per-row GEMV, coalesced) ====================
__global__ void prep_u_k(const float* __restrict__ input, const float* __restrict__ W1,
                         const float* __restrict__ b1) {
    __shared__ float4 inp4[DD / 4];
    int b = blockIdx.x, tid = threadIdx.x;       // 256 threads = 8 warps
    if (tid < 128) inp4[tid] = ((const float4*)(input + (size_t)b * DD))[tid];
    __syncthreads();
    int warp = tid >> 5, lane = tid & 31;
    for (int a = warp; a < DD; a += 8) {
        const float4* w4 = (const float4*)(W1 + (size_t)a * (2 * DD));
        float s = 0.f;
        #pragma unroll
        for (int k = 0; k < 4; k++) {
            float4 wv = w4[lane + 32 * k];       // coalesced 128B per lane-group
            float4 iv = inp4[lane + 32 * k];
            s += wv.x * iv.x + wv.y * iv.y + wv.z * iv.z + wv.w * iv.w;
        }
        #pragma unroll
        for (int o = 16; o > 0; o >>= 1) s += __shfl_xor_sync(0xffffffffu, s, o);
        if (lane == 0) g_u[b * DD + a] = s + b1[a];
    }
}

// ==================== prep: W fp16 round ====================
__global__ void prep_w_k(const float* __restrict__ W1) {
    int base = blockIdx.x * 16384, tid = threadIdx.x;
    for (int i = tid; i < 16384; i += 256) {
        int idx = base + i;
        int a = idx >> 9, j = idx & 511;
        g_whi[idx] = __float2half_rn(W1[(size_t)a * (2 * DD) + DD + j]);
    }
}

__global__ void dummy_k() {}

// ==== GEMM (fp16, 16 warps 4x4, group-private B pipelines) + fused score epilogue ====
__global__ void __launch_bounds__(512, 1)
gemm_k(const float* __restrict__ src, float* __restrict__ scores, const float* __restrict__ W2) {
    extern __shared__ char sm[];
    uint32_t smb = smem_u32(sm);
    int tid = threadIdx.x, lid = tid & 31, wid = tid >> 5;
    int wm = wid & 3, wn = wid >> 2;      // 4 m-warps x 4 n-warp-groups
    int gtid = tid & 127;                 // thread-in-group
    int b = blockIdx.y;
    int s0 = blockIdx.x * 128;

    float* u_sm  = (float*)(sm + U_OFF);
    float* w2_sm = (float*)(sm + W2_OFF);
    u_sm[tid] = g_u[b * DD + tid];
    w2_sm[tid] = W2[tid];

    const float* srcb = src + (size_t)b * DD;   // src[s][b][d]; s-stride = BB*DD

    // ---- load + convert entire A tile (128 x 512 fp32 -> fp16) into smem, once ----
    {
        const int c4 = tid & 127;
        const int rb = tid >> 7;              // 0..3
        #pragma unroll 1
        for (int t8 = 0; t8 < 4; t8++) {
            float4 v[8];
            #pragma unroll
            for (int j = 0; j < 8; j++) {
                int r = rb + 4 * (t8 * 8 + j);
                v[j] = *(const float4*)(srcb + (size_t)(s0 + r) * (BB * DD) + c4 * 4);
            }
            #pragma unroll
            for (int j = 0; j < 8; j++) {
                int r = rb + 4 * (t8 * 8 + j);
                *(uint2*)(sm + A_O + r * A_ROWB + c4 * 8) = make_uint2(
                    packh2(__float2half_rn(v[j].x), __float2half_rn(v[j].y)),
                    packh2(__float2half_rn(v[j].z), __float2half_rn(v[j].w)));
            }
        }
    }

    // ---- group-private B pipeline: this group's 32 n-rows only ----
    const int brow = gtid >> 3, bsg = gtid & 7;   // row 0..15 (t adds 16), seg 0..7
    const uint32_t bdst_lane = smb + B_O + (uint32_t)(wn * GST + brow * ROWB2 + bsg * 16);
    const __half* bsrc_lane = g_whi + (size_t)(wn * 32 + brow) * DD + bsg * 8;

    // prologue: stages 0,1  (f = global chunk index; fnt = f>>3, fck = f&7)
    #pragma unroll
    for (int f = 0; f < NSTAGE - 1; f++) {
        int fnt = f >> 3, fck = f & 7;
        const __half* wsrc = bsrc_lane + (size_t)(fnt * 128) * DD + fck * 64;
        uint32_t dst = bdst_lane + f * STG_ALL;
        cp16(dst, wsrc);
        cp16(dst + 16 * ROWB2, wsrc + (size_t)16 * DD);
        asm volatile("cp.async.commit_group;" ::: "memory");
    }
    __syncthreads();   // A tile + u/w2 visible to everyone

    // hoisted LDSM lane addressing
    const uint32_t a_base = smb + A_O + (uint32_t)((wm * 32 + (lid & 15)) * A_ROWB + (lid >> 4) * 16);
    const uint32_t b_lane = (uint32_t)(((((lid >> 4) << 3) | (lid & 7)) * ROWB2) + ((lid >> 3) & 1) * 16);
    const uint32_t b_grp  = smb + B_O + (uint32_t)(wn * GST) + b_lane;

    float sc[4] = {0.f, 0.f, 0.f, 0.f};
    float acc[2][4][4];
    #pragma unroll
    for (int i = 0; i < 2; i++)
        #pragma unroll
        for (int j = 0; j < 4; j++)
            #pragma unroll
            for (int k = 0; k < 4; k++) acc[i][j][k] = 0.f;

    int st = 0, fst = NSTAGE - 1;
    for (int idx = 0; idx < 32; idx++) {
        int nt = idx >> 3, ck = idx & 7;

        asm volatile("cp.async.wait_group %0;" :: "n"(NSTAGE - 2) : "memory");
        BARG(wn + 1);   // group-scoped barrier: B stage visible within this group

        // prefetch chunk idx+2 into stage fst (always-commit keeps accounting exact)
        {
            int f = idx + NSTAGE - 1;
            if (f < 32) {
                int fnt = f >> 3, fck = f & 7;
                const __half* wsrc = bsrc_lane + (size_t)(fnt * 128) * DD + fck * 64;
                uint32_t dst = bdst_lane + fst * STG_ALL;
                cp16(dst, wsrc);
                cp16(dst + 16 * ROWB2, wsrc + (size_t)16 * DD);
            }
            asm volatile("cp.async.commit_group;" ::: "memory");
        }

        // ---- MMA: A persistent, B from group stage (k = 64 per idx) ----
        {
            uint32_t a_ck = a_base + (uint32_t)(ck * 128);
            uint32_t b_st = b_grp + (uint32_t)(st * STG_ALL);
            #pragma unroll
            for (int ks = 0; ks < 4; ks++) {
                uint32_t af[2][4];
                uint32_t aoff = a_ck + (uint32_t)(ks * 32);
                LDSM4(af[0], aoff);
                LDSM4(af[1], aoff + 16 * A_ROWB);
                #pragma unroll
                for (int p = 0; p < 2; p++) {
                    uint32_t bh[4];
                    LDSM4(bh, b_st + (uint32_t)(p * (16 * ROWB2) + ks * 32));
                    #pragma unroll
                    for (int mt = 0; mt < 2; mt++) {
                        MMA(acc[mt][2 * p],     af[mt], bh);
                        MMA(acc[mt][2 * p + 1], af[mt], bh + 2);
                    }
                }
            }
        }
        st = (st == NSTAGE - 1) ? 0 : st + 1;
        fst = (fst == NSTAGE - 1) ? 0 : fst + 1;

        // ---- nt boundary: fold acc into score partials, reset ----
        if (ck == 7) {
            int tq = lid & 3;
            float part[4] = {0.f, 0.f, 0.f, 0.f};
            #pragma unroll
            for (int j = 0; j < 4; j++) {
                int a = nt * 128 + wn * 32 + j * 8 + tq * 2;
                float u0 = u_sm[a], u1 = u_sm[a + 1];
                float w0 = w2_sm[a], w1 = w2_sm[a + 1];
                #pragma unroll
                for (int mt = 0; mt < 2; mt++) {
                    part[mt * 2 + 0] += w0 * tanh_f(acc[mt][j][0] + u0)
                                      + w1 * tanh_f(acc[mt][j][1] + u1);
                    part[mt * 2 + 1] += w0 * tanh_f(acc[mt][j][2] + u0)
                                      + w1 * tanh_f(acc[mt][j][3] + u1);
                }
            }
            #pragma unroll
            for (int i = 0; i < 4; i++) {
                part[i] += __shfl_xor_sync(0xffffffffu, part[i], 1);
                part[i] += __shfl_xor_sync(0xffffffffu, part[i], 2);
                sc[i] += part[i];
            }
            #pragma unroll
            for (int i = 0; i < 2; i++)
                #pragma unroll
                for (int j = 0; j < 4; j++)
                    #pragma unroll
                    for (int k = 0; k < 4; k++) acc[i][j][k] = 0.f;
        }
    }

    // ---- cross-warp (4 n-warp planes) reduction + store scores ----
    float* red = (float*)(sm + RED_OFF);
    __syncthreads();
    if ((lid & 3) == 0) {
        int g = lid >> 2;
        #pragma unroll
        for (int mt = 0; mt < 2; mt++) {
            red[wn * 128 + wm * 32 + mt * 16 + g]     = sc[mt * 2 + 0];
            red[wn * 128 + wm * 32 + mt * 16 + 8 + g] = sc[mt * 2 + 1];
        }
    }
    __syncthreads();
    if (tid < 128)
        scores[(size_t)(s0 + tid) * BB + b] =
            (red[tid] + red[128 + tid]) + (red[256 + tid] + red[384 + tid]);
}

// ==================== softmax over S (in place) ====================
__global__ void softmax_k(float* __restrict__ attn, const unsigned char* __restrict__ mask) {
    __shared__ float red[256];
    int b = blockIdx.x, tid = threadIdx.x;
    float v[8];
    float mx = -1e30f;
    #pragma unroll
    for (int i = 0; i < 8; i++) {
        int s = tid + i * 256;
        float x = attn[(size_t)s * BB + b];
        if (mask[(size_t)s * BB + b]) x = -1e30f;
        v[i] = x;
        mx = fmaxf(mx, x);
    }
    red[tid] = mx; __syncthreads();
    for (int o = 128; o > 0; o >>= 1) { if (tid < o) red[tid] = fmaxf(red[tid], red[tid + o]); __syncthreads(); }
    mx = red[0]; __syncthreads();
    float sum = 0.f;
    #pragma unroll
    for (int i = 0; i < 8; i++) { v[i] = __expf(v[i] - mx); sum += v[i]; }
    red[tid] = sum; __syncthreads();
    for (int o = 128; o > 0; o >>= 1) { if (tid < o) red[tid] += red[tid + o]; __syncthreads(); }
    float inv = __fdividef(1.f, red[0]);
    #pragma unroll
    for (int i = 0; i < 8; i++) attn[(size_t)(tid + i * 256) * BB + b] = v[i] * inv;
}

// ==================== ctx = sum_s attn[s,b] * src[s,b,:]  (float4, deep MLP) ====================
__global__ void ctx_k(const float* __restrict__ src, const float* __restrict__ attn) {
    int b = blockIdx.x, sch = blockIdx.y, tid = threadIdx.x;   // 128 thr, grid (BB, 8)
    const float4* sp = (const float4*)(src + (size_t)b * DD) + tid;
    int s0 = sch * 256;
    float4 a[8];
    #pragma unroll
    for (int j = 0; j < 8; j++) a[j] = make_float4(0.f, 0.f, 0.f, 0.f);
    #pragma unroll 2
    for (int s = s0; s < s0 + 256; s += 8) {
        #pragma unroll
        for (int j = 0; j < 8; j++) {
            float w = attn[(size_t)(s + j) * BB + b];
            float4 v = sp[(size_t)(s + j) * (BB * DD / 4)];
            a[j].x += w * v.x; a[j].y += w * v.y; a[j].z += w * v.z; a[j].w += w * v.w;
        }
    }
    float4 t;
    t.x = ((a[0].x + a[1].x) + (a[2].x + a[3].x)) + ((a[4].x + a[5].x) + (a[6].x + a[7].x));
    t.y = ((a[0].y + a[1].y) + (a[2].y + a[3].y)) + ((a[4].y + a[5].y) + (a[6].y + a[7].y));
    t.z = ((a[0].z + a[1].z) + (a[2].z + a[3].z)) + ((a[4].z + a[5].z) + (a[6].z + a[7].z));
    t.w = ((a[0].w + a[1].w) + (a[2].w + a[3].w)) + ((a[4].w + a[5].w) + (a[6].w + a[7].w));
    ((float4*)g_part)[((sch * BB + b) << 7) + tid] = t;
}

__global__ void red_k(float* __restrict__ out) {
    int i = blockIdx.x * 512 + threadIdx.x;
    float s = 0.f;
    #pragma unroll
    for (int j = 0; j < 8; j++) s += g_part[j * (BB * DD) + i];
    out[i] = s;
}

// ==================== launch ====================
extern "C" void kernel_launch(void* const* d_in, const int* in_sizes, int n_in,
                              void* d_out, int out_size) {
    (void)in_sizes; (void)n_in; (void)out_size;
    const float* input = (const float*)d_in[0];
    const float* src = (const float*)d_in[1];
    const unsigned char* mask = (const unsigned char*)d_in[2];
    const float* W1 = (const float*)d_in[3];
    const float* b1 = (const float*)d_in[4];
    const float* W2 = (const float*)d_in[5];
    float* out = (float*)d_out;          // [ctx: 64*512][attn: 2048*64]
    float* attn = out + BB * DD;

    cudaFuncSetAttribute(gemm_k, cudaFuncAttributeMaxDynamicSharedMemorySize, DYN_SMEM);

    prep_u_k<<<BB, 256>>>(input, W1, b1);        // launch 1
    prep_w_k<<<16, 256>>>(W1);                   // launch 2
    dummy_k<<<1, 32>>>();                        // launch 3
    gemm_k<<<dim3(16, BB), 512, DYN_SMEM>>>(src, attn, W2);   // launch 4
    softmax_k<<<BB, 256>>>(attn, mask);
    ctx_k<<<dim3(BB, 8), 128>>>(src, attn);
    red_k<<<BB, 512>>>(out);
}

// round 16
// speedup vs baseline: 1.4327x; 1.1054x over previous
#include <cuda_runtime.h>
#include <cuda_fp16.h>
#include <cstdint>

#define SS 2048
#define BB 64
#define DD 512

// ---------------- device scratch (static; no runtime allocs) ----------------
__device__ float g_u[BB * DD];                      // u[b,a] = input.W1x + b1
__device__ __align__(16) __half g_whi[DD * DD];     // W1_src (fp16 rne), K-major [a][d]
__device__ float g_part[16 * BB * DD];              // ctx partials (16 s-slices)
__device__ float g_zpart[16 * BB];                  // Z partials

// ---------------- helpers ----------------
__device__ __forceinline__ uint32_t smem_u32(const void* p) {
    uint32_t a;
    asm("{ .reg .u64 t; cvta.to.shared.u64 t, %1; cvt.u32.u64 %0, t; }" : "=r"(a) : "l"(p));
    return a;
}
__device__ __forceinline__ uint32_t packh2(__half a, __half b) {
    __half2 h = __halves2half2(a, b);
    return *reinterpret_cast<uint32_t*>(&h);
}
__device__ __forceinline__ void cp16(uint32_t dst, const void* src) {
    asm volatile("cp.async.cg.shared.global [%0], [%1], 16;" :: "r"(dst), "l"(src) : "memory");
}
__device__ __forceinline__ float tanh_f(float x) {
    float e = __expf(2.f * x);
    return 1.f - __fdividef(2.f, e + 1.f);
}

#define LDSM4(r, addr) \
    asm volatile("ldmatrix.sync.aligned.m8n8.x4.shared.b16 {%0,%1,%2,%3}, [%4];" \
        : "=r"((r)[0]), "=r"((r)[1]), "=r"((r)[2]), "=r"((r)[3]) : "r"(addr))

#define MMA(d, a, b) \
    asm volatile("mma.sync.aligned.m16n8k16.row.col.f32.f16.f16.f32 " \
        "{%0,%1,%2,%3}, {%4,%5,%6,%7}, {%8,%9}, {%0,%1,%2,%3};" \
        : "+f"((d)[0]), "+f"((d)[1]), "+f"((d)[2]), "+f"((d)[3]) \
        : "r"((a)[0]), "r"((a)[1]), "r"((a)[2]), "r"((a)[3]), "r"((b)[0]), "r"((b)[1]))

#define BARG(id) asm volatile("bar.sync %0, 128;" :: "r"(id) : "memory")

// ---------------- smem layout for gemm_k (R11/R14 proven config) ----------------
#define U_OFF    0
#define W2_OFF   2048
#define RED_OFF  4096            // 4 planes x 128 f = 2048 B
#define A_O      6144
#define A_ROWB   1040            // 512 fp16 = 1024B + 16B pad -> conflict-free LDSM
#define A_SZ     (128 * A_ROWB)  // 133120
#define B_O      (A_O + A_SZ)    // 139264
#define ROWB2    144             // B row: 128B data (k64 fp16) + 16B pad
#define GST      (32 * ROWB2)    // 4608 per group per stage
#define STG_ALL  (4 * GST)       // 18432 per stage (4 groups)
#define NSTAGE   3
#define DYN_SMEM (B_O + NSTAGE * STG_ALL)   // 194560

// ==================== prep (merged): blocks 0..63 u-GEMV, 64..79 W convert ====================
__global__ void prep_k(const float* __restrict__ input, const float* __restrict__ W1,
                       const float* __restrict__ b1) {
    int blk = blockIdx.x, tid = threadIdx.x;    // 256 threads
    if (blk < BB) {
        __shared__ float4 inp4[DD / 4];
        if (tid < 128) inp4[tid] = ((const float4*)(input + (size_t)blk * DD))[tid];
        __syncthreads();
        int warp = tid >> 5, lane = tid & 31;
        for (int a = warp; a < DD; a += 8) {
            const float4* w4 = (const float4*)(W1 + (size_t)a * (2 * DD));
            float s = 0.f;
            #pragma unroll
            for (int k = 0; k < 4; k++) {
                float4 wv = w4[lane + 32 * k];
                float4 iv = inp4[lane + 32 * k];
                s += wv.x * iv.x + wv.y * iv.y + wv.z * iv.z + wv.w * iv.w;
            }
            #pragma unroll
            for (int o = 16; o > 0; o >>= 1) s += __shfl_xor_sync(0xffffffffu, s, o);
            if (lane == 0) g_u[blk * DD + a] = s + b1[a];
        }
    } else {
        int base = (blk - BB) * 16384;
        for (int i = tid; i < 16384; i += 256) {
            int idx = base + i;
            int a = idx >> 9, j = idx & 511;
            g_whi[idx] = __float2half_rn(W1[(size_t)a * (2 * DD) + DD + j]);
        }
    }
}

// ==== GEMM (fp16, 16 warps 4x4, group-private B pipelines) + fused exp(score) epilogue ====
__global__ void __launch_bounds__(512, 1)
gemm_k(const float* __restrict__ src, float* __restrict__ escore, const float* __restrict__ W2) {
    extern __shared__ char sm[];
    uint32_t smb = smem_u32(sm);
    int tid = threadIdx.x, lid = tid & 31, wid = tid >> 5;
    int wm = wid & 3, wn = wid >> 2;      // 4 m-warps x 4 n-warp-groups
    int gtid = tid & 127;                 // thread-in-group
    int b = blockIdx.y;
    int s0 = blockIdx.x * 128;

    float* u_sm  = (float*)(sm + U_OFF);
    float* w2_sm = (float*)(sm + W2_OFF);
    u_sm[tid] = g_u[b * DD + tid];
    w2_sm[tid] = W2[tid];

    const float* srcb = src + (size_t)b * DD;   // src[s][b][d]; s-stride = BB*DD

    // ---- load + convert entire A tile (128 x 512 fp32 -> fp16) into smem, once ----
    {
        const int c4 = tid & 127;
        const int rb = tid >> 7;              // 0..3
        #pragma unroll 1
        for (int t8 = 0; t8 < 4; t8++) {
            float4 v[8];
            #pragma unroll
            for (int j = 0; j < 8; j++) {
                int r = rb + 4 * (t8 * 8 + j);
                v[j] = *(const float4*)(srcb + (size_t)(s0 + r) * (BB * DD) + c4 * 4);
            }
            #pragma unroll
            for (int j = 0; j < 8; j++) {
                int r = rb + 4 * (t8 * 8 + j);
                *(uint2*)(sm + A_O + r * A_ROWB + c4 * 8) = make_uint2(
                    packh2(__float2half_rn(v[j].x), __float2half_rn(v[j].y)),
                    packh2(__float2half_rn(v[j].z), __float2half_rn(v[j].w)));
            }
        }
    }

    // ---- group-private B pipeline: this group's 32 n-rows only ----
    const int brow = gtid >> 3, bsg = gtid & 7;
    const uint32_t bdst_lane = smb + B_O + (uint32_t)(wn * GST + brow * ROWB2 + bsg * 16);
    const __half* bsrc_lane = g_whi + (size_t)(wn * 32 + brow) * DD + bsg * 8;

    #pragma unroll
    for (int f = 0; f < NSTAGE - 1; f++) {
        int fnt = f >> 3, fck = f & 7;
        const __half* wsrc = bsrc_lane + (size_t)(fnt * 128) * DD + fck * 64;
        uint32_t dst = bdst_lane + f * STG_ALL;
        cp16(dst, wsrc);
        cp16(dst + 16 * ROWB2, wsrc + (size_t)16 * DD);
        asm volatile("cp.async.commit_group;" ::: "memory");
    }
    __syncthreads();

    const uint32_t a_base = smb + A_O + (uint32_t)((wm * 32 + (lid & 15)) * A_ROWB + (lid >> 4) * 16);
    const uint32_t b_lane = (uint32_t)(((((lid >> 4) << 3) | (lid & 7)) * ROWB2) + ((lid >> 3) & 1) * 16);
    const uint32_t b_grp  = smb + B_O + (uint32_t)(wn * GST) + b_lane;

    float sc[4] = {0.f, 0.f, 0.f, 0.f};
    float acc[2][4][4];
    #pragma unroll
    for (int i = 0; i < 2; i++)
        #pragma unroll
        for (int j = 0; j < 4; j++)
            #pragma unroll
            for (int k = 0; k < 4; k++) acc[i][j][k] = 0.f;

    int st = 0, fst = NSTAGE - 1;
    for (int idx = 0; idx < 32; idx++) {
        int nt = idx >> 3, ck = idx & 7;

        asm volatile("cp.async.wait_group %0;" :: "n"(NSTAGE - 2) : "memory");
        BARG(wn + 1);

        {
            int f = idx + NSTAGE - 1;
            if (f < 32) {
                int fnt = f >> 3, fck = f & 7;
                const __half* wsrc = bsrc_lane + (size_t)(fnt * 128) * DD + fck * 64;
                uint32_t dst = bdst_lane + fst * STG_ALL;
                cp16(dst, wsrc);
                cp16(dst + 16 * ROWB2, wsrc + (size_t)16 * DD);
            }
            asm volatile("cp.async.commit_group;" ::: "memory");
        }

        {
            uint32_t a_ck = a_base + (uint32_t)(ck * 128);
            uint32_t b_st = b_grp + (uint32_t)(st * STG_ALL);
            #pragma unroll
            for (int ks = 0; ks < 4; ks++) {
                uint32_t af[2][4];
                uint32_t aoff = a_ck + (uint32_t)(ks * 32);
                LDSM4(af[0], aoff);
                LDSM4(af[1], aoff + 16 * A_ROWB);
                #pragma unroll
                for (int p = 0; p < 2; p++) {
                    uint32_t bh[4];
                    LDSM4(bh, b_st + (uint32_t)(p * (16 * ROWB2) + ks * 32));
                    #pragma unroll
                    for (int mt = 0; mt < 2; mt++) {
                        MMA(acc[mt][2 * p],     af[mt], bh);
                        MMA(acc[mt][2 * p + 1], af[mt], bh + 2);
                    }
                }
            }
        }
        st = (st == NSTAGE - 1) ? 0 : st + 1;
        fst = (fst == NSTAGE - 1) ? 0 : fst + 1;

        if (ck == 7) {
            int tq = lid & 3;
            float part[4] = {0.f, 0.f, 0.f, 0.f};
            #pragma unroll
            for (int j = 0; j < 4; j++) {
                int a = nt * 128 + wn * 32 + j * 8 + tq * 2;
                float u0 = u_sm[a], u1 = u_sm[a + 1];
                float w0 = w2_sm[a], w1 = w2_sm[a + 1];
                #pragma unroll
                for (int mt = 0; mt < 2; mt++) {
                    part[mt * 2 + 0] += w0 * tanh_f(acc[mt][j][0] + u0)
                                      + w1 * tanh_f(acc[mt][j][1] + u1);
                    part[mt * 2 + 1] += w0 * tanh_f(acc[mt][j][2] + u0)
                                      + w1 * tanh_f(acc[mt][j][3] + u1);
                }
            }
            #pragma unroll
            for (int i = 0; i < 4; i++) {
                part[i] += __shfl_xor_sync(0xffffffffu, part[i], 1);
                part[i] += __shfl_xor_sync(0xffffffffu, part[i], 2);
                sc[i] += part[i];
            }
            #pragma unroll
            for (int i = 0; i < 2; i++)
                #pragma unroll
                for (int j = 0; j < 4; j++)
                    #pragma unroll
                    for (int k = 0; k < 4; k++) acc[i][j][k] = 0.f;
        }
    }

    // ---- cross-warp reduction + store e = exp(score)  (softmax is shift-free: |score|<=51) ----
    float* red = (float*)(sm + RED_OFF);
    __syncthreads();
    if ((lid & 3) == 0) {
        int g = lid >> 2;
        #pragma unroll
        for (int mt = 0; mt < 2; mt++) {
            red[wn * 128 + wm * 32 + mt * 16 + g]     = sc[mt * 2 + 0];
            red[wn * 128 + wm * 32 + mt * 16 + 8 + g] = sc[mt * 2 + 1];
        }
    }
    __syncthreads();
    if (tid < 128) {
        float total = (red[tid] + red[128 + tid]) + (red[256 + tid] + red[384 + tid]);
        escore[(size_t)(s0 + tid) * BB + b] = __expf(total);
    }
}

// ======= ctx partials: P = sum_s e*src, Z = sum_s e  (grid (BB,16), 128 thr) =======
__global__ void ctx_k(const float* __restrict__ src, const float* __restrict__ e,
                      const unsigned char* __restrict__ mask) {
    int b = blockIdx.x, sch = blockIdx.y, tid = threadIdx.x;
    const float4* sp = (const float4*)(src + (size_t)b * DD) + tid;
    int s0 = sch * 128;
    float4 a[8];
    #pragma unroll
    for (int j = 0; j < 8; j++) a[j] = make_float4(0.f, 0.f, 0.f, 0.f);
    float zp = 0.f;
    #pragma unroll 2
    for (int s = s0; s < s0 + 128; s += 8) {
        #pragma unroll
        for (int j = 0; j < 8; j++) {
            float w = e[(size_t)(s + j) * BB + b];
            if (mask[(size_t)(s + j) * BB + b]) w = 0.f;
            zp += w;
            float4 v = sp[(size_t)(s + j) * (BB * DD / 4)];
            a[j].x += w * v.x; a[j].y += w * v.y; a[j].z += w * v.z; a[j].w += w * v.w;
        }
    }
    float4 t;
    t.x = ((a[0].x + a[1].x) + (a[2].x + a[3].x)) + ((a[4].x + a[5].x) + (a[6].x + a[7].x));
    t.y = ((a[0].y + a[1].y) + (a[2].y + a[3].y)) + ((a[4].y + a[5].y) + (a[6].y + a[7].y));
    t.z = ((a[0].z + a[1].z) + (a[2].z + a[3].z)) + ((a[4].z + a[5].z) + (a[6].z + a[7].z));
    t.w = ((a[0].w + a[1].w) + (a[2].w + a[3].w)) + ((a[4].w + a[5].w) + (a[6].w + a[7].w));
    ((float4*)g_part)[((sch * BB + b) << 7) + tid] = t;
    if (tid == 0) g_zpart[sch * BB + b] = zp;
}

// ======= finalize: blocks 0..63 ctx=P/Z; blocks 64..319 attn=e_masked/Z (512 thr) =======
__global__ void fin_k(float* __restrict__ out, const unsigned char* __restrict__ mask) {
    float* attn = out + BB * DD;
    int blk = blockIdx.x, tid = threadIdx.x;
    if (blk < BB) {
        int b = blk;
        float z = 0.f;
        #pragma unroll
        for (int j = 0; j < 16; j++) z += g_zpart[j * BB + b];
        float s = 0.f;
        #pragma unroll
        for (int j = 0; j < 16; j++) s += g_part[(size_t)(j * BB + b) * DD + tid];
        out[b * DD + tid] = s / z;
    } else {
        int g = (blk - BB) * 512 + tid;     // 0..131071 over [s][b]
        int b = g & 63;
        float z = 0.f;
        #pragma unroll
        for (int j = 0; j < 16; j++) z += g_zpart[j * BB + b];
        float ev = attn[g];
        if (mask[g]) ev = 0.f;
        attn[g] = ev / z;
    }
}

// ==================== launch ====================
extern "C" void kernel_launch(void* const* d_in, const int* in_sizes, int n_in,
                              void* d_out, int out_size) {
    (void)in_sizes; (void)n_in; (void)out_size;
    const float* input = (const float*)d_in[0];
    const float* src = (const float*)d_in[1];
    const unsigned char* mask = (const unsigned char*)d_in[2];
    const float* W1 = (const float*)d_in[3];
    const float* b1 = (const float*)d_in[4];
    const float* W2 = (const float*)d_in[5];
    float* out = (float*)d_out;          // [ctx: 64*512][attn: 2048*64]
    float* escore = out + BB * DD;       // e = exp(score) staged in attn region

    cudaFuncSetAttribute(gemm_k, cudaFuncAttributeMaxDynamicSharedMemorySize, DYN_SMEM);

    prep_k<<<80, 256>>>(input, W1, b1);                       // 1
    gemm_k<<<dim3(16, BB), 512, DYN_SMEM>>>(src, escore, W2); // 2
    ctx_k<<<dim3(BB, 16), 128>>>(src, escore, mask);          // 3
    fin_k<<<320, 512>>>(out, mask);                           // 4
}